// round 5
// baseline (speedup 1.0000x reference)
#include <cuda_runtime.h>
#include <stdint.h>

// GazeOnce360 post-processing, round 5:
//   K1 scan:   prefilter + exact softmax score -> per-bin buckets (single pass).
//   K2 finish: suffix-scan hist -> cutoff B -> atomic-free gather with exact
//              per-bin ranks -> intra-bin rank-sort (no bitonic) -> decode.
//   K3 mask:   512x512 IoU suppression bitmask.
//   K4 nms:    word-at-a-time warp greedy NMS; batched-OR suppression apply.

#define KDET 512
#define NBINS 8192
#define BIN_BASE (0x3F666667u >> 8)   // bits of smallest float > 0.9f, >>8
#define SLOTS 128                     // per-bin capacity (expected max ~60)
#define CAND_CAP 1024
#define WLCAP 1024

__device__ unsigned int       g_hist[NBINS];          // slot counters (==hist)
__device__ unsigned long long g_bins[NBINS * SLOTS];  // bucket store
__device__ float4             g_cand[KDET];
__device__ float              g_score[KDET];
__device__ unsigned int       g_mask[KDET * 16];

// ---------------- K1: fused scan -> per-bin buckets ----------------
// softmax(c0,c1)[1] == 1/(exp(c0-c1)+1) exactly when c1>c0 (max-subtracted, e1=1).
// Prefilter d>2.19 (< ln9; sigmoid(2.19)=0.8993) skips expf for ~94% of lanes.
__global__ void __launch_bounds__(512) k_scan(const float4* __restrict__ conf4,
                                              int nPairs) {
    int base = blockIdx.x * (512 * 8) + threadIdx.x;
    float4 f[8];
#pragma unroll
    for (int k = 0; k < 8; k++) {
        int idx = base + k * 512;
        f[k] = (idx < nPairs) ? conf4[idx] : make_float4(0.f, 0.f, 0.f, 0.f);
    }
#pragma unroll
    for (int k = 0; k < 8; k++) {
        int pidx = base + k * 512;
#pragma unroll
        for (int q = 0; q < 2; q++) {
            float c0 = q ? f[k].z : f[k].x;
            float c1 = q ? f[k].w : f[k].y;
            if (c1 - c0 > 2.19f && pidx < nPairs) {
                float e0 = expf(c0 - c1);
                float s  = 1.0f / (e0 + 1.0f);
                if (s > 0.9f) {
                    unsigned bits = __float_as_uint(s);
                    unsigned bin  = (bits >> 8) - BIN_BASE;
                    unsigned slot = atomicAdd(&g_hist[bin], 1u);
                    if (slot < SLOTS) {
                        unsigned ei = 2u * (unsigned)pidx + (unsigned)q;
                        g_bins[bin * SLOTS + slot] =
                            ((unsigned long long)bits << 32)
                          | (unsigned long long)(0xFFFFFFFFu - ei);
                    }
                }
            }
        }
    }
}

// ---------------- K2: select + gather + intra-bin rank sort + decode ----------
__global__ void __launch_bounds__(512) k_finish(const float4* __restrict__ loc4,
                                                const float4* __restrict__ pri4) {
    __shared__ unsigned ssum[512];
    __shared__ unsigned sB, snw;
    __shared__ unsigned wbin[WLCAP], wbase[WLCAP], wcnt[WLCAP];
    __shared__ unsigned long long sk[CAND_CAP];   // gathered, bin-grouped
    __shared__ unsigned long long sk2[CAND_CAP];  // fully sorted
    __shared__ unsigned sinfo[CAND_CAP];          // (base<<16)|cnt per slot
    int t = threadIdx.x;
    if (t == 0) { sB = 0u; snw = 0u; }
    sk[t] = 0ULL;  sk[t + 512] = 0ULL;
    sk2[t] = 0ULL; sk2[t + 512] = 0ULL;
    sinfo[t] = 0u; sinfo[t + 512] = 0u;

    // per-thread bins 16t..16t+15; suffix sums at 16-bin granularity
    unsigned h[16];
    unsigned psum = 0;
#pragma unroll
    for (int j = 0; j < 16; j++) { h[j] = g_hist[t * 16 + j]; psum += h[j]; }
    ssum[t] = psum;
    __syncthreads();
    for (int off = 1; off < 512; off <<= 1) {
        unsigned v = (t + off < 512) ? ssum[t + off] : 0u;
        __syncthreads();
        ssum[t] += v;
        __syncthreads();
    }

    // B = max bin with suffix-count >= 512 (else 0)
    {
        unsigned cum = (t < 511) ? ssum[t + 1] : 0u;
        int best = -1;
#pragma unroll
        for (int j = 15; j >= 0; j--) {
            cum += h[j];
            if (cum >= KDET) { best = t * 16 + j; break; }
        }
        if (best >= 0) atomicMax(&sB, (unsigned)best);
    }
    __syncthreads();
    unsigned B = sB;

    // worklist of active bins >= B with exact output base (descending order):
    // base(bin) = number of keys in strictly higher bins
    {
        unsigned suf = (t < 511) ? ssum[t + 1] : 0u;
#pragma unroll
        for (int j = 15; j >= 0; j--) {
            unsigned b = (unsigned)t * 16 + (unsigned)j;
            if (b >= B && h[j] > 0 && suf < CAND_CAP) {
                unsigned e = atomicAdd(&snw, 1u);       // smem atomics, ~#bins
                if (e < WLCAP) {
                    wbin[e] = b; wbase[e] = suf;
                    wcnt[e] = min(min(h[j], (unsigned)SLOTS),
                                  (unsigned)CAND_CAP - suf);
                }
            }
            suf += h[j];
        }
    }
    __syncthreads();

    // warp-cooperative gather; record bin extent per slot
    {
        int wid = t >> 5, lane = t & 31;
        unsigned nw = min(snw, (unsigned)WLCAP);
        for (unsigned e = wid; e < nw; e += 16) {
            unsigned bin = wbin[e], bs = wbase[e], cn = wcnt[e];
            for (unsigned k = lane; k < cn; k += 32) {
                unsigned p = bs + k;
                sk[p] = g_bins[bin * SLOTS + k];
                sinfo[p] = (bs << 16) | cn;
            }
        }
    }
    __syncthreads();

    // intra-bin rank sort: final pos = base + #{greater keys in bin}
#pragma unroll
    for (int r = 0; r < 2; r++) {
        int p = t + r * 512;
        unsigned long long key = sk[p];
        if (key) {
            unsigned info = sinfo[p];
            unsigned bs = info >> 16, cn = info & 0xFFFFu;
            unsigned rank = 0;
            for (unsigned k = 0; k < cn; k++)
                rank += (sk[bs + k] > key) ? 1u : 0u;
            sk2[bs + rank] = key;
        }
    }
    __syncthreads();

    // decode top 512
    {
        unsigned long long key = sk2[t];
        unsigned sb = (unsigned)(key >> 32);
        float4 c = make_float4(0.f, 0.f, 0.f, 0.f);
        float sc = 0.f;
        if (sb) {
            unsigned idx = 0xFFFFFFFFu - (unsigned)(key & 0xFFFFFFFFull);
            float4 l = loc4[idx];
            float4 p = pri4[idx];
            float cx = p.x + (l.x * 0.1f) * p.z;
            float cy = p.y + (l.y * 0.1f) * p.w;
            float w  = p.z * expf(l.z * 0.2f);
            float hh = p.w * expf(l.w * 0.2f);
            float x1 = cx - w * 0.5f;
            float y1 = cy - hh * 0.5f;
            float x2 = x1 + w;
            float y2 = y1 + hh;
            c = make_float4(x1 * 2048.f, y1 * 2048.f, x2 * 2048.f, y2 * 2048.f);
            sc = __uint_as_float(sb);
        }
        g_cand[t]  = c;
        g_score[t] = sc;
    }
}

// ---------------- K3: 512x512 suppression bitmask -----------------
__global__ void __launch_bounds__(256) k_mask() {
    int w = blockIdx.x * blockDim.x + threadIdx.x;     // 0..8191
    int i = w >> 4, c = w & 15;
    float4 bi = g_cand[i];
    float areai = (bi.z - bi.x + 1.f) * (bi.w - bi.y + 1.f);
    unsigned bits = 0u;
#pragma unroll 4
    for (int b = 0; b < 32; b++) {
        int j = c * 32 + b;
        float4 bj = g_cand[j];
        float areaj = (bj.z - bj.x + 1.f) * (bj.w - bj.y + 1.f);
        float xx1 = fmaxf(bi.x, bj.x), yy1 = fmaxf(bi.y, bj.y);
        float xx2 = fminf(bi.z, bj.z), yy2 = fminf(bi.w, bj.w);
        float ww = fmaxf(xx2 - xx1 + 1.f, 0.f);
        float hh = fmaxf(yy2 - yy1 + 1.f, 0.f);
        float inter = ww * hh;
        float iou = inter / (areai + areaj - inter);
        if (iou > 0.4f && j > i) bits |= (1u << b);
    }
    g_mask[w] = bits;
}

// ---------------- K4: warp NMS (batched-OR apply) + output; re-zero hist -----
__global__ void __launch_bounds__(512) k_nms_out(float* __restrict__ out) {
    __shared__ unsigned smask[KDET * 16];              // 8KB
    __shared__ unsigned skeep[16];
    int t = threadIdx.x;

    // restore scratch invariant for next launch
    {
        uint4* hz = (uint4*)g_hist;
#pragma unroll
        for (int i = 0; i < 4; i++)
            hz[t + i * 512] = make_uint4(0u, 0u, 0u, 0u);
    }
    for (int i = t; i < KDET * 4; i += 512)
        ((uint4*)smask)[i] = ((const uint4*)g_mask)[i];

    bool k0 = g_score[t] > 0.0f;                       // keep0 = top_s > 0
    unsigned wball = __ballot_sync(0xFFFFFFFFu, k0);
    if ((t & 31) == 0) skeep[t >> 5] = wball;
    __syncthreads();

    if (t < 32) {
        unsigned L = (unsigned)t & 15u;                // lanes 16-31 mirror 0-15
        unsigned kw = skeep[L];
        unsigned mi[32];                               // own word's intra columns
#pragma unroll
        for (int j = 0; j < 32; j++)
            mi[j] = smask[(32u * L + j) * 16u + L];

        for (int w = 0; w < 16; w++) {
            // speculative intra-word greedy resolve (only lane w's is used)
            unsigned cur = kw;
#pragma unroll
            for (int j = 0; j < 32; j++) {
                unsigned tm = (unsigned)(((int)(cur << (31 - j))) >> 31);
                cur &= ~(mi[j] & tm);
            }
            unsigned acc = __shfl_sync(0xFFFFFFFFu, cur, w);
            // batched OR of accepted rows' suppression (loads pipeline; no
            // load->kw loop-carried chain)
            unsigned sup = 0u, a = acc;
            while (a) {
                int b = __ffs(a) - 1;
                a &= a - 1;
                sup |= smask[(32u * w + (unsigned)b) * 16u + L];
            }
            kw &= ~sup;
            if ((int)L == w) kw = cur;                 // word w: final value
        }
        if (t < 16) skeep[L] = kw;
    }
    __syncthreads();

    unsigned kept = (skeep[t >> 5] >> (t & 31)) & 1u;
    float4 c = g_cand[t];
    float sc = g_score[t];
    const float inv = 1.0f / 2048.0f;
    float o0 = 0.f, o1 = 0.f, o2 = 0.f, o3 = 0.f, o4 = 0.f;
    if (kept) { o0 = c.x * inv; o1 = c.y * inv; o2 = c.z * inv; o3 = c.w * inv; o4 = sc; }
    out[t * 5 + 0] = o0;
    out[t * 5 + 1] = o1;
    out[t * 5 + 2] = o2;
    out[t * 5 + 3] = o3;
    out[t * 5 + 4] = o4;
}

extern "C" void kernel_launch(void* const* d_in, const int* in_sizes, int n_in,
                              void* d_out, int out_size) {
    const float4* loc4  = (const float4*)d_in[0];
    const float4* conf4 = (const float4*)d_in[1];
    const float4* pri4  = (const float4*)d_in[2];
    float* out = (float*)d_out;

    int nElem  = in_sizes[1] / 2;                   // N priors
    int nPairs = (nElem + 1) / 2;                   // float4 count of conf
    int scanBlocks = (nPairs + 4095) / 4096;        // 8 float4 per thread

    k_scan<<<scanBlocks, 512>>>(conf4, nPairs);
    k_finish<<<1, 512>>>(loc4, pri4);
    k_mask<<<(KDET * 16) / 256, 256>>>();
    k_nms_out<<<1, 512>>>(out);
}

// round 6
// speedup vs baseline: 1.6987x; 1.6987x over previous
#include <cuda_runtime.h>
#include <stdint.h>

// GazeOnce360 post-processing, round 6:
//   K1 scan:   prefilter + exact softmax score -> per-bin buckets (single pass).
//   K2 finish: suffix-scan hist -> cutoff B -> atomic-free gather with exact
//              per-bin ranks -> intra-bin rank-sort -> decode.
//   K3 mask:   512x512 IoU suppression bitmask.
//   K4 nms:    greedy scan restricted to rows with NONZERO mask (nzr bitmap) --
//              zero-mask rows are no-ops, so the serial chain shrinks from ~500
//              rows to the handful of actual conflicts.

#define KDET 512
#define NBINS 8192
#define BIN_BASE (0x3F666667u >> 8)   // bits of smallest float > 0.9f, >>8
#define SLOTS 128                     // per-bin capacity (expected max ~60)
#define CAND_CAP 1024
#define WLCAP 1024

__device__ unsigned int       g_hist[NBINS];          // slot counters (==hist)
__device__ unsigned long long g_bins[NBINS * SLOTS];  // bucket store
__device__ float4             g_cand[KDET];
__device__ float              g_score[KDET];
__device__ unsigned int       g_mask[KDET * 16];

// ---------------- K1: fused scan -> per-bin buckets ----------------
// softmax(c0,c1)[1] == 1/(exp(c0-c1)+1) exactly when c1>c0 (max-subtracted, e1=1).
// Prefilter d>2.19 (< ln9; sigmoid(2.19)=0.8993) skips expf for ~94% of lanes.
__global__ void __launch_bounds__(512) k_scan(const float4* __restrict__ conf4,
                                              int nPairs) {
    int base = blockIdx.x * (512 * 8) + threadIdx.x;
    float4 f[8];
#pragma unroll
    for (int k = 0; k < 8; k++) {
        int idx = base + k * 512;
        f[k] = (idx < nPairs) ? conf4[idx] : make_float4(0.f, 0.f, 0.f, 0.f);
    }
#pragma unroll
    for (int k = 0; k < 8; k++) {
        int pidx = base + k * 512;
#pragma unroll
        for (int q = 0; q < 2; q++) {
            float c0 = q ? f[k].z : f[k].x;
            float c1 = q ? f[k].w : f[k].y;
            if (c1 - c0 > 2.19f && pidx < nPairs) {
                float e0 = expf(c0 - c1);
                float s  = 1.0f / (e0 + 1.0f);
                if (s > 0.9f) {
                    unsigned bits = __float_as_uint(s);
                    unsigned bin  = (bits >> 8) - BIN_BASE;
                    unsigned slot = atomicAdd(&g_hist[bin], 1u);
                    if (slot < SLOTS) {
                        unsigned ei = 2u * (unsigned)pidx + (unsigned)q;
                        g_bins[bin * SLOTS + slot] =
                            ((unsigned long long)bits << 32)
                          | (unsigned long long)(0xFFFFFFFFu - ei);
                    }
                }
            }
        }
    }
}

// ---------------- K2: select + gather + intra-bin rank sort + decode ----------
__global__ void __launch_bounds__(512) k_finish(const float4* __restrict__ loc4,
                                                const float4* __restrict__ pri4) {
    __shared__ unsigned ssum[512];
    __shared__ unsigned sB, snw;
    __shared__ unsigned wbin[WLCAP], wbase[WLCAP], wcnt[WLCAP];
    __shared__ unsigned long long sk[CAND_CAP];   // gathered, bin-grouped
    __shared__ unsigned long long sk2[CAND_CAP];  // fully sorted
    __shared__ unsigned sinfo[CAND_CAP];          // (base<<16)|cnt per slot
    int t = threadIdx.x;
    if (t == 0) { sB = 0u; snw = 0u; }
    sk[t] = 0ULL;  sk[t + 512] = 0ULL;
    sk2[t] = 0ULL; sk2[t + 512] = 0ULL;
    sinfo[t] = 0u; sinfo[t + 512] = 0u;

    // per-thread bins 16t..16t+15; suffix sums at 16-bin granularity
    unsigned h[16];
    unsigned psum = 0;
#pragma unroll
    for (int j = 0; j < 16; j++) { h[j] = g_hist[t * 16 + j]; psum += h[j]; }
    ssum[t] = psum;
    __syncthreads();
    for (int off = 1; off < 512; off <<= 1) {
        unsigned v = (t + off < 512) ? ssum[t + off] : 0u;
        __syncthreads();
        ssum[t] += v;
        __syncthreads();
    }

    // B = max bin with suffix-count >= 512 (else 0)
    {
        unsigned cum = (t < 511) ? ssum[t + 1] : 0u;
        int best = -1;
#pragma unroll
        for (int j = 15; j >= 0; j--) {
            cum += h[j];
            if (cum >= KDET) { best = t * 16 + j; break; }
        }
        if (best >= 0) atomicMax(&sB, (unsigned)best);
    }
    __syncthreads();
    unsigned B = sB;

    // worklist of active bins >= B with exact output base (descending order):
    // base(bin) = number of keys in strictly higher bins
    {
        unsigned suf = (t < 511) ? ssum[t + 1] : 0u;
#pragma unroll
        for (int j = 15; j >= 0; j--) {
            unsigned b = (unsigned)t * 16 + (unsigned)j;
            if (b >= B && h[j] > 0 && suf < CAND_CAP) {
                unsigned e = atomicAdd(&snw, 1u);       // smem atomics, ~#bins
                if (e < WLCAP) {
                    wbin[e] = b; wbase[e] = suf;
                    wcnt[e] = min(min(h[j], (unsigned)SLOTS),
                                  (unsigned)CAND_CAP - suf);
                }
            }
            suf += h[j];
        }
    }
    __syncthreads();

    // warp-cooperative gather; record bin extent per slot
    {
        int wid = t >> 5, lane = t & 31;
        unsigned nw = min(snw, (unsigned)WLCAP);
        for (unsigned e = wid; e < nw; e += 16) {
            unsigned bin = wbin[e], bs = wbase[e], cn = wcnt[e];
            for (unsigned k = lane; k < cn; k += 32) {
                unsigned p = bs + k;
                sk[p] = g_bins[bin * SLOTS + k];
                sinfo[p] = (bs << 16) | cn;
            }
        }
    }
    __syncthreads();

    // intra-bin rank sort: final pos = base + #{greater keys in bin}
#pragma unroll
    for (int r = 0; r < 2; r++) {
        int p = t + r * 512;
        unsigned long long key = sk[p];
        if (key) {
            unsigned info = sinfo[p];
            unsigned bs = info >> 16, cn = info & 0xFFFFu;
            unsigned rank = 0;
            for (unsigned k = 0; k < cn; k++)
                rank += (sk[bs + k] > key) ? 1u : 0u;
            sk2[bs + rank] = key;
        }
    }
    __syncthreads();

    // decode top 512
    {
        unsigned long long key = sk2[t];
        unsigned sb = (unsigned)(key >> 32);
        float4 c = make_float4(0.f, 0.f, 0.f, 0.f);
        float sc = 0.f;
        if (sb) {
            unsigned idx = 0xFFFFFFFFu - (unsigned)(key & 0xFFFFFFFFull);
            float4 l = loc4[idx];
            float4 p = pri4[idx];
            float cx = p.x + (l.x * 0.1f) * p.z;
            float cy = p.y + (l.y * 0.1f) * p.w;
            float w  = p.z * expf(l.z * 0.2f);
            float hh = p.w * expf(l.w * 0.2f);
            float x1 = cx - w * 0.5f;
            float y1 = cy - hh * 0.5f;
            float x2 = x1 + w;
            float y2 = y1 + hh;
            c = make_float4(x1 * 2048.f, y1 * 2048.f, x2 * 2048.f, y2 * 2048.f);
            sc = __uint_as_float(sb);
        }
        g_cand[t]  = c;
        g_score[t] = sc;
    }
}

// ---------------- K3: 512x512 suppression bitmask -----------------
__global__ void __launch_bounds__(256) k_mask() {
    int w = blockIdx.x * blockDim.x + threadIdx.x;     // 0..8191
    int i = w >> 4, c = w & 15;
    float4 bi = g_cand[i];
    float areai = (bi.z - bi.x + 1.f) * (bi.w - bi.y + 1.f);
    unsigned bits = 0u;
#pragma unroll 4
    for (int b = 0; b < 32; b++) {
        int j = c * 32 + b;
        float4 bj = g_cand[j];
        float areaj = (bj.z - bj.x + 1.f) * (bj.w - bj.y + 1.f);
        float xx1 = fmaxf(bi.x, bj.x), yy1 = fmaxf(bi.y, bj.y);
        float xx2 = fminf(bi.z, bj.z), yy2 = fminf(bi.w, bj.w);
        float ww = fmaxf(xx2 - xx1 + 1.f, 0.f);
        float hh = fmaxf(yy2 - yy1 + 1.f, 0.f);
        float inter = ww * hh;
        float iou = inter / (areai + areaj - inter);
        if (iou > 0.4f && j > i) bits |= (1u << b);
    }
    g_mask[w] = bits;
}

// ---------------- K4: conflict-skip greedy NMS + output; re-zero hist --------
__global__ void __launch_bounds__(512) k_nms_out(float* __restrict__ out) {
    __shared__ unsigned smask[KDET * 16];              // 8KB
    __shared__ unsigned skeep[16];
    __shared__ unsigned snz[16];                       // rows with nonzero mask
    int t = threadIdx.x;

    // restore scratch invariant for next launch
    {
        uint4* hz = (uint4*)g_hist;
#pragma unroll
        for (int i = 0; i < 4; i++)
            hz[t + i * 512] = make_uint4(0u, 0u, 0u, 0u);
    }
    for (int i = t; i < KDET * 4; i += 512)
        ((uint4*)smask)[i] = ((const uint4*)g_mask)[i];
    __syncthreads();

    // per-row nonzero-mask flag (thread t owns row t) + keep0 ballot
    {
        const uint4* mr = (const uint4*)&smask[t * 16];
        uint4 a = mr[0], b = mr[1], c = mr[2], d = mr[3];
        unsigned ro = a.x | a.y | a.z | a.w | b.x | b.y | b.z | b.w
                    | c.x | c.y | c.z | c.w | d.x | d.y | d.z | d.w;
        unsigned nzb = __ballot_sync(0xFFFFFFFFu, ro != 0u);
        bool k0 = g_score[t] > 0.0f;                   // keep0 = top_s > 0
        unsigned kb = __ballot_sync(0xFFFFFFFFu, k0);
        if ((t & 31) == 0) { snz[t >> 5] = nzb; skeep[t >> 5] = kb; }
    }
    __syncthreads();

    // sequential greedy over CONFLICT rows only (kept & nonzero-mask).
    // Zero-mask rows suppress nothing -> skipping them is exact.
    if (t == 0) {
        unsigned kw[16];
#pragma unroll
        for (int w = 0; w < 16; w++) kw[w] = skeep[w];
#pragma unroll
        for (int w = 0; w < 16; w++) {
            unsigned cur = kw[w] & snz[w];
            while (cur) {
                int bit = __ffs(cur) - 1;
                int i = w * 32 + bit;
                cur &= cur - 1;                        // row i processed
                const uint4* mr = (const uint4*)&smask[i * 16];
                uint4 m0 = mr[0], m1 = mr[1], m2 = mr[2], m3 = mr[3];
                kw[0]  &= ~m0.x; kw[1]  &= ~m0.y; kw[2]  &= ~m0.z; kw[3]  &= ~m0.w;
                kw[4]  &= ~m1.x; kw[5]  &= ~m1.y; kw[6]  &= ~m1.z; kw[7]  &= ~m1.w;
                kw[8]  &= ~m2.x; kw[9]  &= ~m2.y; kw[10] &= ~m2.z; kw[11] &= ~m2.w;
                kw[12] &= ~m3.x; kw[13] &= ~m3.y; kw[14] &= ~m3.z; kw[15] &= ~m3.w;
                cur &= kw[w];                          // drop newly suppressed
            }
        }
#pragma unroll
        for (int w = 0; w < 16; w++) skeep[w] = kw[w];
    }
    __syncthreads();

    unsigned kept = (skeep[t >> 5] >> (t & 31)) & 1u;
    float4 c = g_cand[t];
    float sc = g_score[t];
    const float inv = 1.0f / 2048.0f;
    float o0 = 0.f, o1 = 0.f, o2 = 0.f, o3 = 0.f, o4 = 0.f;
    if (kept) { o0 = c.x * inv; o1 = c.y * inv; o2 = c.z * inv; o3 = c.w * inv; o4 = sc; }
    out[t * 5 + 0] = o0;
    out[t * 5 + 1] = o1;
    out[t * 5 + 2] = o2;
    out[t * 5 + 3] = o3;
    out[t * 5 + 4] = o4;
}

extern "C" void kernel_launch(void* const* d_in, const int* in_sizes, int n_in,
                              void* d_out, int out_size) {
    const float4* loc4  = (const float4*)d_in[0];
    const float4* conf4 = (const float4*)d_in[1];
    const float4* pri4  = (const float4*)d_in[2];
    float* out = (float*)d_out;

    int nElem  = in_sizes[1] / 2;                   // N priors
    int nPairs = (nElem + 1) / 2;                   // float4 count of conf
    int scanBlocks = (nPairs + 4095) / 4096;        // 8 float4 per thread

    k_scan<<<scanBlocks, 512>>>(conf4, nPairs);
    k_finish<<<1, 512>>>(loc4, pri4);
    k_mask<<<(KDET * 16) / 256, 256>>>();
    k_nms_out<<<1, 512>>>(out);
}

// round 7
// speedup vs baseline: 1.9635x; 1.1559x over previous
#include <cuda_runtime.h>
#include <stdint.h>

// GazeOnce360 post-processing, round 7:
//   K1 scan:   prefilter + exact softmax score -> per-bin buckets (single pass).
//   K2 finish: suffix-scan hist -> cutoff B -> atomic-free gather -> intra-bin
//              rank-sort -> decode.
//   K3 mask:   512x512 IoU SUPPRESSOR mask (bit i set for row j iff i<j and
//              iou>0.4), stored transposed [word][row] for conflict-free LDS.
//   K4 nms:    parallel Jacobi fixpoint of the greedy recurrence (exact; antitone
//              sandwich argument) -- no sequential row scan.

#define KDET 512
#define NBINS 8192
#define BIN_BASE (0x3F666667u >> 8)   // bits of smallest float > 0.9f, >>8
#define SLOTS 128                     // per-bin capacity (expected max ~60)
#define CAND_CAP 1024
#define WLCAP 1024

__device__ unsigned int       g_hist[NBINS];          // slot counters (==hist)
__device__ unsigned long long g_bins[NBINS * SLOTS];  // bucket store
__device__ float4             g_cand[KDET];
__device__ float              g_score[KDET];
__device__ unsigned int       g_sup[16 * KDET];       // [word w][row j]: suppressors

// ---------------- K1: fused scan -> per-bin buckets ----------------
// softmax(c0,c1)[1] == 1/(exp(c0-c1)+1) exactly when c1>c0 (max-subtracted, e1=1).
// Prefilter d>2.19 (< ln9; sigmoid(2.19)=0.8993) skips expf for ~94% of lanes.
__global__ void __launch_bounds__(512) k_scan(const float4* __restrict__ conf4,
                                              int nPairs) {
    int base = blockIdx.x * (512 * 8) + threadIdx.x;
    float4 f[8];
#pragma unroll
    for (int k = 0; k < 8; k++) {
        int idx = base + k * 512;
        f[k] = (idx < nPairs) ? conf4[idx] : make_float4(0.f, 0.f, 0.f, 0.f);
    }
#pragma unroll
    for (int k = 0; k < 8; k++) {
        int pidx = base + k * 512;
#pragma unroll
        for (int q = 0; q < 2; q++) {
            float c0 = q ? f[k].z : f[k].x;
            float c1 = q ? f[k].w : f[k].y;
            if (c1 - c0 > 2.19f && pidx < nPairs) {
                float e0 = expf(c0 - c1);
                float s  = 1.0f / (e0 + 1.0f);
                if (s > 0.9f) {
                    unsigned bits = __float_as_uint(s);
                    unsigned bin  = (bits >> 8) - BIN_BASE;
                    unsigned slot = atomicAdd(&g_hist[bin], 1u);
                    if (slot < SLOTS) {
                        unsigned ei = 2u * (unsigned)pidx + (unsigned)q;
                        g_bins[bin * SLOTS + slot] =
                            ((unsigned long long)bits << 32)
                          | (unsigned long long)(0xFFFFFFFFu - ei);
                    }
                }
            }
        }
    }
}

// ---------------- K2: select + gather + intra-bin rank sort + decode ----------
__global__ void __launch_bounds__(512) k_finish(const float4* __restrict__ loc4,
                                                const float4* __restrict__ pri4) {
    __shared__ unsigned ssum[512];
    __shared__ unsigned sB, snw;
    __shared__ unsigned wbin[WLCAP], wbase[WLCAP], wcnt[WLCAP];
    __shared__ unsigned long long sk[CAND_CAP];   // gathered, bin-grouped
    __shared__ unsigned long long sk2[CAND_CAP];  // fully sorted
    __shared__ unsigned sinfo[CAND_CAP];          // (base<<16)|cnt per slot
    int t = threadIdx.x;
    if (t == 0) { sB = 0u; snw = 0u; }
    sk[t] = 0ULL;  sk[t + 512] = 0ULL;
    sk2[t] = 0ULL; sk2[t + 512] = 0ULL;
    sinfo[t] = 0u; sinfo[t + 512] = 0u;

    // per-thread bins 16t..16t+15; suffix sums at 16-bin granularity
    unsigned h[16];
    unsigned psum = 0;
#pragma unroll
    for (int j = 0; j < 16; j++) { h[j] = g_hist[t * 16 + j]; psum += h[j]; }
    ssum[t] = psum;
    __syncthreads();
    for (int off = 1; off < 512; off <<= 1) {
        unsigned v = (t + off < 512) ? ssum[t + off] : 0u;
        __syncthreads();
        ssum[t] += v;
        __syncthreads();
    }

    // B = max bin with suffix-count >= 512 (else 0)
    {
        unsigned cum = (t < 511) ? ssum[t + 1] : 0u;
        int best = -1;
#pragma unroll
        for (int j = 15; j >= 0; j--) {
            cum += h[j];
            if (cum >= KDET) { best = t * 16 + j; break; }
        }
        if (best >= 0) atomicMax(&sB, (unsigned)best);
    }
    __syncthreads();
    unsigned B = sB;

    // worklist of active bins >= B with exact output base (descending order)
    {
        unsigned suf = (t < 511) ? ssum[t + 1] : 0u;
#pragma unroll
        for (int j = 15; j >= 0; j--) {
            unsigned b = (unsigned)t * 16 + (unsigned)j;
            if (b >= B && h[j] > 0 && suf < CAND_CAP) {
                unsigned e = atomicAdd(&snw, 1u);
                if (e < WLCAP) {
                    wbin[e] = b; wbase[e] = suf;
                    wcnt[e] = min(min(h[j], (unsigned)SLOTS),
                                  (unsigned)CAND_CAP - suf);
                }
            }
            suf += h[j];
        }
    }
    __syncthreads();

    // warp-cooperative gather; record bin extent per slot
    {
        int wid = t >> 5, lane = t & 31;
        unsigned nw = min(snw, (unsigned)WLCAP);
        for (unsigned e = wid; e < nw; e += 16) {
            unsigned bin = wbin[e], bs = wbase[e], cn = wcnt[e];
            for (unsigned k = lane; k < cn; k += 32) {
                unsigned p = bs + k;
                sk[p] = g_bins[bin * SLOTS + k];
                sinfo[p] = (bs << 16) | cn;
            }
        }
    }
    __syncthreads();

    // intra-bin rank sort: final pos = base + #{greater keys in bin}
#pragma unroll
    for (int r = 0; r < 2; r++) {
        int p = t + r * 512;
        unsigned long long key = sk[p];
        if (key) {
            unsigned info = sinfo[p];
            unsigned bs = info >> 16, cn = info & 0xFFFFu;
            unsigned rank = 0;
            for (unsigned k = 0; k < cn; k++)
                rank += (sk[bs + k] > key) ? 1u : 0u;
            sk2[bs + rank] = key;
        }
    }
    __syncthreads();

    // decode top 512
    {
        unsigned long long key = sk2[t];
        unsigned sb = (unsigned)(key >> 32);
        float4 c = make_float4(0.f, 0.f, 0.f, 0.f);
        float sc = 0.f;
        if (sb) {
            unsigned idx = 0xFFFFFFFFu - (unsigned)(key & 0xFFFFFFFFull);
            float4 l = loc4[idx];
            float4 p = pri4[idx];
            float cx = p.x + (l.x * 0.1f) * p.z;
            float cy = p.y + (l.y * 0.1f) * p.w;
            float w  = p.z * expf(l.z * 0.2f);
            float hh = p.w * expf(l.w * 0.2f);
            float x1 = cx - w * 0.5f;
            float y1 = cy - hh * 0.5f;
            float x2 = x1 + w;
            float y2 = y1 + hh;
            c = make_float4(x1 * 2048.f, y1 * 2048.f, x2 * 2048.f, y2 * 2048.f);
            sc = __uint_as_float(sb);
        }
        g_cand[t]  = c;
        g_score[t] = sc;
    }
}

// ---------------- K3: suppressor bitmask, transposed layout ----------------
// thread id = c*512 + r: row r, suppressor chunk c (cols 32c..32c+31).
// bit b set iff iou(r, j)>0.4 and j<r  (j = 32c+b). Write g_sup[c*512+r].
__global__ void __launch_bounds__(256) k_mask() {
    int w = blockIdx.x * blockDim.x + threadIdx.x;     // 0..8191
    int r = w & 511, c = w >> 9;
    float4 bi = g_cand[r];
    float areai = (bi.z - bi.x + 1.f) * (bi.w - bi.y + 1.f);
    unsigned bits = 0u;
#pragma unroll 4
    for (int b = 0; b < 32; b++) {
        int j = c * 32 + b;
        float4 bj = g_cand[j];
        float areaj = (bj.z - bj.x + 1.f) * (bj.w - bj.y + 1.f);
        float xx1 = fmaxf(bi.x, bj.x), yy1 = fmaxf(bi.y, bj.y);
        float xx2 = fminf(bi.z, bj.z), yy2 = fminf(bi.w, bj.w);
        float ww = fmaxf(xx2 - xx1 + 1.f, 0.f);
        float hh = fmaxf(yy2 - yy1 + 1.f, 0.f);
        float inter = ww * hh;
        float iou = inter / (areai + areaj - inter);
        if (iou > 0.4f && j < r) bits |= (1u << b);
    }
    g_sup[c * 512 + r] = bits;
}

// ---------------- K4: parallel Jacobi greedy NMS + output; re-zero hist ------
// K_{t+1}[j] = keep0[j] & !OR_{i<j}(K_t[i] & sup[i][j]); K_0 = keep0.
// f antitone => even iterates >= greedy >= odd iterates; consecutive equal
// iterates (one even, one odd) pin the greedy fixpoint exactly.
__global__ void __launch_bounds__(512) k_nms_out(float* __restrict__ out) {
    __shared__ unsigned ssup[16 * KDET];               // [w][j], conflict-free
    __shared__ unsigned skeep[16];
    int t = threadIdx.x;

    // restore scratch invariant for next launch
    {
        uint4* hz = (uint4*)g_hist;
#pragma unroll
        for (int i = 0; i < 4; i++)
            hz[t + i * 512] = make_uint4(0u, 0u, 0u, 0u);
    }
    for (int i = t; i < KDET * 4; i += 512)
        ((uint4*)ssup)[i] = ((const uint4*)g_sup)[i];

    bool k0 = g_score[t] > 0.0f;                       // keep0 = top_s > 0
    {
        unsigned kb = __ballot_sync(0xFFFFFFFFu, k0);
        if ((t & 31) == 0) skeep[t >> 5] = kb;
    }
    __syncthreads();

    bool mykeep = k0;
    for (int iter = 0; iter < KDET; iter++) {
        unsigned sup = 0u;
#pragma unroll
        for (int w = 0; w < 16; w++)
            sup |= ssup[w * KDET + t] & skeep[w];
        bool nk = k0 && (sup == 0u);
        int changed = __syncthreads_or((int)(nk != mykeep));  // barrier: reads done
        mykeep = nk;
        unsigned nw = __ballot_sync(0xFFFFFFFFu, nk);
        if ((t & 31) == 0) skeep[t >> 5] = nw;
        __syncthreads();                                      // writes visible
        if (!changed) break;
    }

    float4 c = g_cand[t];
    float sc = g_score[t];
    const float inv = 1.0f / 2048.0f;
    float o0 = 0.f, o1 = 0.f, o2 = 0.f, o3 = 0.f, o4 = 0.f;
    if (mykeep) { o0 = c.x * inv; o1 = c.y * inv; o2 = c.z * inv; o3 = c.w * inv; o4 = sc; }
    out[t * 5 + 0] = o0;
    out[t * 5 + 1] = o1;
    out[t * 5 + 2] = o2;
    out[t * 5 + 3] = o3;
    out[t * 5 + 4] = o4;
}

extern "C" void kernel_launch(void* const* d_in, const int* in_sizes, int n_in,
                              void* d_out, int out_size) {
    const float4* loc4  = (const float4*)d_in[0];
    const float4* conf4 = (const float4*)d_in[1];
    const float4* pri4  = (const float4*)d_in[2];
    float* out = (float*)d_out;

    int nElem  = in_sizes[1] / 2;                   // N priors
    int nPairs = (nElem + 1) / 2;                   // float4 count of conf
    int scanBlocks = (nPairs + 4095) / 4096;        // 8 float4 per thread

    k_scan<<<scanBlocks, 512>>>(conf4, nPairs);
    k_finish<<<1, 512>>>(loc4, pri4);
    k_mask<<<(KDET * 16) / 256, 256>>>();
    k_nms_out<<<1, 512>>>(out);
}

// round 8
// speedup vs baseline: 1.9938x; 1.0154x over previous
#include <cuda_runtime.h>
#include <stdint.h>

// GazeOnce360 post-processing, round 8: TWO kernels.
//   K1 scan+finish: conf scan -> per-bin buckets; LAST-DONE block runs the
//       select/gather/rank-sort/decode inline (threadfence+counter pattern).
//   K2 mask+nms: 16 blocks x 512 compute the suppressor bitmask (1 word/thread,
//       transposed layout); LAST-DONE block runs an exact 16-step forward word
//       sweep (intra-word Jacobi resolve per warp), writes output, re-zeroes
//       scratch counters for graph replay determinism.

#define KDET 512
#define NBINS 8192
#define BIN_BASE (0x3F666667u >> 8)   // bits of smallest float > 0.9f, >>8
#define SLOTS 128                     // per-bin capacity (expected max ~50)
#define CAND_CAP 1024
#define WLCAP 1024

__device__ unsigned int       g_hist[NBINS];          // slot counters (==hist)
__device__ unsigned long long g_bins[NBINS * SLOTS];  // bucket store
__device__ float4             g_cand[KDET];
__device__ float              g_score[KDET];
__device__ unsigned int       g_sup[16 * KDET];       // [word w][row r]: suppressors of r
__device__ unsigned int       g_done1, g_done2;       // last-block counters

// =================== K1: scan -> buckets; last block finishes ===============
// softmax(c0,c1)[1] == 1/(exp(c0-c1)+1) exactly when c1>c0 (max-subtracted, e1=1).
// Prefilter d>2.19 (< ln9; sigmoid(2.19)=0.8993) skips expf for ~94% of lanes.
__global__ void __launch_bounds__(512) k_scan_finish(const float4* __restrict__ conf4,
                                                     const float4* __restrict__ loc4,
                                                     const float4* __restrict__ pri4,
                                                     int nPairs) {
    int t = threadIdx.x;

    // ---------------- scan phase ----------------
    {
        int base = blockIdx.x * (512 * 8) + t;
        float4 f[8];
#pragma unroll
        for (int k = 0; k < 8; k++) {
            int idx = base + k * 512;
            f[k] = (idx < nPairs) ? conf4[idx] : make_float4(0.f, 0.f, 0.f, 0.f);
        }
#pragma unroll
        for (int k = 0; k < 8; k++) {
            int pidx = base + k * 512;
#pragma unroll
            for (int q = 0; q < 2; q++) {
                float c0 = q ? f[k].z : f[k].x;
                float c1 = q ? f[k].w : f[k].y;
                if (c1 - c0 > 2.19f && pidx < nPairs) {
                    float e0 = expf(c0 - c1);
                    float s  = 1.0f / (e0 + 1.0f);
                    if (s > 0.9f) {
                        unsigned bits = __float_as_uint(s);
                        unsigned bin  = (bits >> 8) - BIN_BASE;
                        unsigned slot = atomicAdd(&g_hist[bin], 1u);
                        if (slot < SLOTS) {
                            unsigned ei = 2u * (unsigned)pidx + (unsigned)q;
                            g_bins[bin * SLOTS + slot] =
                                ((unsigned long long)bits << 32)
                              | (unsigned long long)(0xFFFFFFFFu - ei);
                        }
                    }
                }
            }
        }
    }

    // ---------------- last-block election ----------------
    __shared__ unsigned s_last;
    __syncthreads();
    if (t == 0) {
        __threadfence();
        unsigned old = atomicAdd(&g_done1, 1u);
        s_last = (old == gridDim.x - 1) ? 1u : 0u;
    }
    __syncthreads();
    if (!s_last) return;
    __threadfence();

    // ---------------- finish phase (whole block) ----------------
    __shared__ unsigned ssum[512];
    __shared__ unsigned sB, snw;
    __shared__ unsigned wbin[WLCAP], wbase[WLCAP], wcnt[WLCAP];
    __shared__ unsigned long long sk[CAND_CAP];   // gathered, bin-grouped
    __shared__ unsigned long long sk2[CAND_CAP];  // fully sorted
    __shared__ unsigned sinfo[CAND_CAP];          // (base<<16)|cnt per slot
    if (t == 0) { sB = 0u; snw = 0u; }
    sk[t] = 0ULL;  sk[t + 512] = 0ULL;
    sk2[t] = 0ULL; sk2[t + 512] = 0ULL;
    sinfo[t] = 0u; sinfo[t + 512] = 0u;

    unsigned h[16];
    unsigned psum = 0;
#pragma unroll
    for (int j = 0; j < 16; j++) { h[j] = g_hist[t * 16 + j]; psum += h[j]; }
    ssum[t] = psum;
    __syncthreads();
    for (int off = 1; off < 512; off <<= 1) {
        unsigned v = (t + off < 512) ? ssum[t + off] : 0u;
        __syncthreads();
        ssum[t] += v;
        __syncthreads();
    }

    // B = max bin with suffix-count >= 512 (else 0)
    {
        unsigned cum = (t < 511) ? ssum[t + 1] : 0u;
        int best = -1;
#pragma unroll
        for (int j = 15; j >= 0; j--) {
            cum += h[j];
            if (cum >= KDET) { best = t * 16 + j; break; }
        }
        if (best >= 0) atomicMax(&sB, (unsigned)best);
    }
    __syncthreads();
    unsigned B = sB;

    // worklist of active bins >= B with exact output base (descending order)
    {
        unsigned suf = (t < 511) ? ssum[t + 1] : 0u;
#pragma unroll
        for (int j = 15; j >= 0; j--) {
            unsigned b = (unsigned)t * 16 + (unsigned)j;
            if (b >= B && h[j] > 0 && suf < CAND_CAP) {
                unsigned e = atomicAdd(&snw, 1u);
                if (e < WLCAP) {
                    wbin[e] = b; wbase[e] = suf;
                    wcnt[e] = min(min(h[j], (unsigned)SLOTS),
                                  (unsigned)CAND_CAP - suf);
                }
            }
            suf += h[j];
        }
    }
    __syncthreads();

    // warp-cooperative gather; record bin extent per slot
    {
        int wid = t >> 5, lane = t & 31;
        unsigned nw = min(snw, (unsigned)WLCAP);
        for (unsigned e = wid; e < nw; e += 16) {
            unsigned bin = wbin[e], bs = wbase[e], cn = wcnt[e];
            for (unsigned k = lane; k < cn; k += 32) {
                unsigned p = bs + k;
                sk[p] = g_bins[bin * SLOTS + k];
                sinfo[p] = (bs << 16) | cn;
            }
        }
    }
    __syncthreads();

    // intra-bin rank sort: final pos = base + #{greater keys in bin}
#pragma unroll
    for (int r = 0; r < 2; r++) {
        int p = t + r * 512;
        unsigned long long key = sk[p];
        if (key) {
            unsigned info = sinfo[p];
            unsigned bs = info >> 16, cn = info & 0xFFFFu;
            unsigned rank = 0;
            for (unsigned k = 0; k < cn; k++)
                rank += (sk[bs + k] > key) ? 1u : 0u;
            sk2[bs + rank] = key;
        }
    }
    __syncthreads();

    // decode top 512
    {
        unsigned long long key = sk2[t];
        unsigned sb = (unsigned)(key >> 32);
        float4 c = make_float4(0.f, 0.f, 0.f, 0.f);
        float sc = 0.f;
        if (sb) {
            unsigned idx = 0xFFFFFFFFu - (unsigned)(key & 0xFFFFFFFFull);
            float4 l = loc4[idx];
            float4 p = pri4[idx];
            float cx = p.x + (l.x * 0.1f) * p.z;
            float cy = p.y + (l.y * 0.1f) * p.w;
            float w  = p.z * expf(l.z * 0.2f);
            float hh = p.w * expf(l.w * 0.2f);
            float x1 = cx - w * 0.5f;
            float y1 = cy - hh * 0.5f;
            float x2 = x1 + w;
            float y2 = y1 + hh;
            c = make_float4(x1 * 2048.f, y1 * 2048.f, x2 * 2048.f, y2 * 2048.f);
            sc = __uint_as_float(sb);
        }
        g_cand[t]  = c;
        g_score[t] = sc;
    }
}

// =================== K2: mask (16 blocks); last block does NMS ==============
// Block c computes suppressor word chunk c for all 512 rows (coalesced writes).
// bit b of g_sup[c*512+r]: j=32c+b suppresses r (j<r and iou>0.4).
__global__ void __launch_bounds__(512) k_mask_nms(float* __restrict__ out) {
    int t = threadIdx.x;
    int c = blockIdx.x;                               // 0..15

    float4 bi = g_cand[t];
    float sc = g_score[t];
    {
        float areai = (bi.z - bi.x + 1.f) * (bi.w - bi.y + 1.f);
        unsigned bits = 0u;
#pragma unroll 4
        for (int b = 0; b < 32; b++) {
            int j = c * 32 + b;
            float4 bj = g_cand[j];
            float areaj = (bj.z - bj.x + 1.f) * (bj.w - bj.y + 1.f);
            float xx1 = fmaxf(bi.x, bj.x), yy1 = fmaxf(bi.y, bj.y);
            float xx2 = fminf(bi.z, bj.z), yy2 = fminf(bi.w, bj.w);
            float ww = fmaxf(xx2 - xx1 + 1.f, 0.f);
            float hh = fmaxf(yy2 - yy1 + 1.f, 0.f);
            float inter = ww * hh;
            float iou = inter / (areai + areaj - inter);
            if (iou > 0.4f && j < t) bits |= (1u << b);
        }
        g_sup[c * 512 + t] = bits;
    }

    // last-block election
    __shared__ unsigned s_last;
    __syncthreads();
    if (t == 0) {
        __threadfence();
        unsigned old = atomicAdd(&g_done2, 1u);
        s_last = (old == gridDim.x - 1) ? 1u : 0u;
    }
    __syncthreads();
    if (!s_last) return;
    __threadfence();

    // -------- forward word sweep: exact greedy in 16 steps --------
    unsigned supw[16];                                // row t's suppressors (regs)
#pragma unroll
    for (int w = 0; w < 16; w++) supw[w] = g_sup[w * 512 + t];
    int wme = t >> 5, lane = t & 31;
    unsigned intra = g_sup[wme * 512 + t];            // own-word suppressors
    bool k0 = sc > 0.0f;                              // keep0 = top_s > 0
    unsigned below = (1u << lane) - 1u;

    __shared__ unsigned skeep[16];
    bool suppressed = false;
#pragma unroll
    for (int w = 0; w < 16; w++) {
        if (wme == w) {
            // intra-word greedy via word-local Jacobi; terminates <=33 iters by
            // strict lower-index dependency; consecutive-equal pins the fixpoint
            unsigned tent = __ballot_sync(0xFFFFFFFFu, k0 && !suppressed);
            unsigned fcur = tent, prev;
            do {
                prev = fcur;
                bool killed = (intra & fcur & below) != 0u;
                fcur = __ballot_sync(0xFFFFFFFFu, !killed) & tent;
            } while (fcur != prev);
            if (lane == 0) skeep[w] = fcur;
        }
        __syncthreads();
        suppressed = suppressed || ((supw[w] & skeep[w]) != 0u);
    }

    unsigned kept = (skeep[wme] >> lane) & 1u;
    const float inv = 1.0f / 2048.0f;                 // exact (power of 2)
    float o0 = 0.f, o1 = 0.f, o2 = 0.f, o3 = 0.f, o4 = 0.f;
    if (kept) { o0 = bi.x * inv; o1 = bi.y * inv; o2 = bi.z * inv; o3 = bi.w * inv; o4 = sc; }
    out[t * 5 + 0] = o0;
    out[t * 5 + 1] = o1;
    out[t * 5 + 2] = o2;
    out[t * 5 + 3] = o3;
    out[t * 5 + 4] = o4;

    // restore scratch invariants for next graph replay
    {
        uint4* hz = (uint4*)g_hist;
#pragma unroll
        for (int i = 0; i < 4; i++)
            hz[t + i * 512] = make_uint4(0u, 0u, 0u, 0u);
    }
    if (t == 0) { g_done1 = 0u; g_done2 = 0u; }
}

extern "C" void kernel_launch(void* const* d_in, const int* in_sizes, int n_in,
                              void* d_out, int out_size) {
    const float4* loc4  = (const float4*)d_in[0];
    const float4* conf4 = (const float4*)d_in[1];
    const float4* pri4  = (const float4*)d_in[2];
    float* out = (float*)d_out;

    int nElem  = in_sizes[1] / 2;                   // N priors
    int nPairs = (nElem + 1) / 2;                   // float4 count of conf
    int scanBlocks = (nPairs + 4095) / 4096;        // 8 float4 per thread

    k_scan_finish<<<scanBlocks, 512>>>(conf4, loc4, pri4, nPairs);
    k_mask_nms<<<16, 512>>>(out);
}

// round 9
// speedup vs baseline: 2.3388x; 1.1730x over previous
#include <cuda_runtime.h>
#include <stdint.h>

// GazeOnce360 post-processing, round 9: TWO kernels.
//   K1 scan+finish: conf scan -> per-bin buckets; LAST-DONE block runs
//       select/gather/rank-sort/decode inline.
//   K2 mask+nms: 16 blocks x 512; suppressor bitmask computed from SMEM-staged
//       boxes+areas with division-free IoU compare; LAST-DONE block runs the
//       exact 16-step forward word sweep and writes output.

#define KDET 512
#define NBINS 8192
#define BIN_BASE (0x3F666667u >> 8)   // bits of smallest float > 0.9f, >>8
#define SLOTS 128                     // per-bin capacity (expected max ~50)
#define CAND_CAP 1024
#define WLCAP 1024

__device__ unsigned int       g_hist[NBINS];          // slot counters (==hist)
__device__ unsigned long long g_bins[NBINS * SLOTS];  // bucket store
__device__ float4             g_cand[KDET];
__device__ float              g_score[KDET];
__device__ unsigned int       g_sup[16 * KDET];       // [word w][row r]: suppressors of r
__device__ unsigned int       g_done1, g_done2;       // last-block counters

// =================== K1: scan -> buckets; last block finishes ===============
// softmax(c0,c1)[1] == 1/(exp(c0-c1)+1) exactly when c1>c0 (max-subtracted, e1=1).
// Prefilter d>2.19 (< ln9; sigmoid(2.19)=0.8993) skips expf for ~94% of lanes.
__global__ void __launch_bounds__(512) k_scan_finish(const float4* __restrict__ conf4,
                                                     const float4* __restrict__ loc4,
                                                     const float4* __restrict__ pri4,
                                                     int nPairs) {
    int t = threadIdx.x;

    // ---------------- scan phase ----------------
    {
        int base = blockIdx.x * (512 * 8) + t;
        float4 f[8];
#pragma unroll
        for (int k = 0; k < 8; k++) {
            int idx = base + k * 512;
            f[k] = (idx < nPairs) ? conf4[idx] : make_float4(0.f, 0.f, 0.f, 0.f);
        }
#pragma unroll
        for (int k = 0; k < 8; k++) {
            int pidx = base + k * 512;
#pragma unroll
            for (int q = 0; q < 2; q++) {
                float c0 = q ? f[k].z : f[k].x;
                float c1 = q ? f[k].w : f[k].y;
                if (c1 - c0 > 2.19f && pidx < nPairs) {
                    float e0 = expf(c0 - c1);
                    float s  = 1.0f / (e0 + 1.0f);
                    if (s > 0.9f) {
                        unsigned bits = __float_as_uint(s);
                        unsigned bin  = (bits >> 8) - BIN_BASE;
                        unsigned slot = atomicAdd(&g_hist[bin], 1u);
                        if (slot < SLOTS) {
                            unsigned ei = 2u * (unsigned)pidx + (unsigned)q;
                            g_bins[bin * SLOTS + slot] =
                                ((unsigned long long)bits << 32)
                              | (unsigned long long)(0xFFFFFFFFu - ei);
                        }
                    }
                }
            }
        }
    }

    // ---------------- last-block election ----------------
    __shared__ unsigned s_last;
    __syncthreads();
    if (t == 0) {
        __threadfence();
        unsigned old = atomicAdd(&g_done1, 1u);
        s_last = (old == gridDim.x - 1) ? 1u : 0u;
    }
    __syncthreads();
    if (!s_last) return;
    __threadfence();

    // ---------------- finish phase (whole block) ----------------
    __shared__ unsigned ssum[512];
    __shared__ unsigned sB, snw;
    __shared__ unsigned wbin[WLCAP], wbase[WLCAP], wcnt[WLCAP];
    __shared__ unsigned long long sk[CAND_CAP];   // gathered, bin-grouped
    __shared__ unsigned long long sk2[CAND_CAP];  // fully sorted
    __shared__ unsigned sinfo[CAND_CAP];          // (base<<16)|cnt per slot
    if (t == 0) { sB = 0u; snw = 0u; }
    sk[t] = 0ULL;  sk[t + 512] = 0ULL;
    sk2[t] = 0ULL; sk2[t + 512] = 0ULL;
    sinfo[t] = 0u; sinfo[t + 512] = 0u;

    unsigned h[16];
    unsigned psum = 0;
#pragma unroll
    for (int j = 0; j < 16; j++) { h[j] = g_hist[t * 16 + j]; psum += h[j]; }
    ssum[t] = psum;
    __syncthreads();
    for (int off = 1; off < 512; off <<= 1) {
        unsigned v = (t + off < 512) ? ssum[t + off] : 0u;
        __syncthreads();
        ssum[t] += v;
        __syncthreads();
    }

    // B = max bin with suffix-count >= 512 (else 0)
    {
        unsigned cum = (t < 511) ? ssum[t + 1] : 0u;
        int best = -1;
#pragma unroll
        for (int j = 15; j >= 0; j--) {
            cum += h[j];
            if (cum >= KDET) { best = t * 16 + j; break; }
        }
        if (best >= 0) atomicMax(&sB, (unsigned)best);
    }
    __syncthreads();
    unsigned B = sB;

    // worklist of active bins >= B with exact output base (descending order)
    {
        unsigned suf = (t < 511) ? ssum[t + 1] : 0u;
#pragma unroll
        for (int j = 15; j >= 0; j--) {
            unsigned b = (unsigned)t * 16 + (unsigned)j;
            if (b >= B && h[j] > 0 && suf < CAND_CAP) {
                unsigned e = atomicAdd(&snw, 1u);
                if (e < WLCAP) {
                    wbin[e] = b; wbase[e] = suf;
                    wcnt[e] = min(min(h[j], (unsigned)SLOTS),
                                  (unsigned)CAND_CAP - suf);
                }
            }
            suf += h[j];
        }
    }
    __syncthreads();

    // warp-cooperative gather; record bin extent per slot
    {
        int wid = t >> 5, lane = t & 31;
        unsigned nw = min(snw, (unsigned)WLCAP);
        for (unsigned e = wid; e < nw; e += 16) {
            unsigned bin = wbin[e], bs = wbase[e], cn = wcnt[e];
            for (unsigned k = lane; k < cn; k += 32) {
                unsigned p = bs + k;
                sk[p] = g_bins[bin * SLOTS + k];
                sinfo[p] = (bs << 16) | cn;
            }
        }
    }
    __syncthreads();

    // intra-bin rank sort: final pos = base + #{greater keys in bin}
#pragma unroll
    for (int r = 0; r < 2; r++) {
        int p = t + r * 512;
        unsigned long long key = sk[p];
        if (key) {
            unsigned info = sinfo[p];
            unsigned bs = info >> 16, cn = info & 0xFFFFu;
            unsigned rank = 0;
            for (unsigned k = 0; k < cn; k++)
                rank += (sk[bs + k] > key) ? 1u : 0u;
            sk2[bs + rank] = key;
        }
    }
    __syncthreads();

    // decode top 512
    {
        unsigned long long key = sk2[t];
        unsigned sb = (unsigned)(key >> 32);
        float4 c = make_float4(0.f, 0.f, 0.f, 0.f);
        float sc = 0.f;
        if (sb) {
            unsigned idx = 0xFFFFFFFFu - (unsigned)(key & 0xFFFFFFFFull);
            float4 l = loc4[idx];
            float4 p = pri4[idx];
            float cx = p.x + (l.x * 0.1f) * p.z;
            float cy = p.y + (l.y * 0.1f) * p.w;
            float w  = p.z * expf(l.z * 0.2f);
            float hh = p.w * expf(l.w * 0.2f);
            float x1 = cx - w * 0.5f;
            float y1 = cy - hh * 0.5f;
            float x2 = x1 + w;
            float y2 = y1 + hh;
            c = make_float4(x1 * 2048.f, y1 * 2048.f, x2 * 2048.f, y2 * 2048.f);
            sc = __uint_as_float(sb);
        }
        g_cand[t]  = c;
        g_score[t] = sc;
    }
}

// =================== K2: mask (16 blocks); last block does NMS ==============
// Division-free IoU: iou>0.4  <=>  inter > 0.4*(areai+areaj-inter)
// (denominator > 0 since each area >= 1). Boxes+areas staged in SMEM.
__global__ void __launch_bounds__(512) k_mask_nms(float* __restrict__ out) {
    __shared__ float4 scand[KDET];     // 8KB
    __shared__ float  sarea[KDET];     // 2KB
    int t = threadIdx.x;
    int c = blockIdx.x;                               // 0..15

    float4 bi = g_cand[t];
    float sc = g_score[t];
    scand[t] = bi;
    float areai = (bi.z - bi.x + 1.f) * (bi.w - bi.y + 1.f);
    sarea[t] = areai;
    __syncthreads();

    {
        unsigned bits = 0u;
#pragma unroll 8
        for (int b = 0; b < 32; b++) {
            int j = c * 32 + b;
            float4 bj = scand[j];
            float xx1 = fmaxf(bi.x, bj.x), yy1 = fmaxf(bi.y, bj.y);
            float xx2 = fminf(bi.z, bj.z), yy2 = fminf(bi.w, bj.w);
            float ww = fmaxf(xx2 - xx1 + 1.f, 0.f);
            float hh = fmaxf(yy2 - yy1 + 1.f, 0.f);
            float inter = ww * hh;
            // inter > 0.4*(areai+areaj-inter), denominator strictly positive
            bool s = inter > 0.4f * (areai + sarea[j] - inter);
            if (s && j < t) bits |= (1u << b);
        }
        g_sup[c * 512 + t] = bits;
    }

    // last-block election
    __shared__ unsigned s_last;
    __syncthreads();
    if (t == 0) {
        __threadfence();
        unsigned old = atomicAdd(&g_done2, 1u);
        s_last = (old == gridDim.x - 1) ? 1u : 0u;
    }
    __syncthreads();
    if (!s_last) return;
    __threadfence();

    // -------- forward word sweep: exact greedy in 16 steps --------
    unsigned supw[16];                                // row t's suppressors (regs)
#pragma unroll
    for (int w = 0; w < 16; w++) supw[w] = g_sup[w * 512 + t];
    int wme = t >> 5, lane = t & 31;
    unsigned intra = g_sup[wme * 512 + t];            // own-word suppressors
    bool k0 = sc > 0.0f;                              // keep0 = top_s > 0
    unsigned below = (1u << lane) - 1u;

    __shared__ unsigned skeep[16];
    bool suppressed = false;
#pragma unroll
    for (int w = 0; w < 16; w++) {
        if (wme == w) {
            // intra-word greedy via word-local Jacobi (terminates <=33 iters by
            // strict lower-index dependency; consecutive-equal pins fixpoint)
            unsigned tent = __ballot_sync(0xFFFFFFFFu, k0 && !suppressed);
            unsigned fcur = tent, prev;
            do {
                prev = fcur;
                bool killed = (intra & fcur & below) != 0u;
                fcur = __ballot_sync(0xFFFFFFFFu, !killed) & tent;
            } while (fcur != prev);
            if (lane == 0) skeep[w] = fcur;
        }
        __syncthreads();
        suppressed = suppressed || ((supw[w] & skeep[w]) != 0u);
    }

    unsigned kept = (skeep[wme] >> lane) & 1u;
    const float inv = 1.0f / 2048.0f;                 // exact (power of 2)
    float o0 = 0.f, o1 = 0.f, o2 = 0.f, o3 = 0.f, o4 = 0.f;
    if (kept) { o0 = bi.x * inv; o1 = bi.y * inv; o2 = bi.z * inv; o3 = bi.w * inv; o4 = sc; }
    out[t * 5 + 0] = o0;
    out[t * 5 + 1] = o1;
    out[t * 5 + 2] = o2;
    out[t * 5 + 3] = o3;
    out[t * 5 + 4] = o4;

    // restore scratch invariants for next graph replay
    {
        uint4* hz = (uint4*)g_hist;
#pragma unroll
        for (int i = 0; i < 4; i++)
            hz[t + i * 512] = make_uint4(0u, 0u, 0u, 0u);
    }
    if (t == 0) { g_done1 = 0u; g_done2 = 0u; }
}

extern "C" void kernel_launch(void* const* d_in, const int* in_sizes, int n_in,
                              void* d_out, int out_size) {
    const float4* loc4  = (const float4*)d_in[0];
    const float4* conf4 = (const float4*)d_in[1];
    const float4* pri4  = (const float4*)d_in[2];
    float* out = (float*)d_out;

    int nElem  = in_sizes[1] / 2;                   // N priors
    int nPairs = (nElem + 1) / 2;                   // float4 count of conf
    int scanBlocks = (nPairs + 4095) / 4096;        // 8 float4 per thread

    k_scan_finish<<<scanBlocks, 512>>>(conf4, loc4, pri4, nPairs);
    k_mask_nms<<<16, 512>>>(out);
}